// round 5
// baseline (speedup 1.0000x reference)
#include <cuda_runtime.h>
#include <cuda_bf16.h>
#include <math.h>
#include <stdint.h>

// Problem constants
#define BATCH 8192
#define DIN   1025
#define HID   1024
#define NACT  1026
#define NHEAD 513
#define KSEQ  32

// Padded dims
#define DINP  1056   // DIN padded to mult of 32
#define NACTP 1152   // NACT padded to mult of 128

// ---------------------------------------------------------------------------
// Scratch (allocation-free: __device__ globals)
// ---------------------------------------------------------------------------
__device__ __nv_bfloat16 g_Shi[(size_t)BATCH * DINP];
__device__ __nv_bfloat16 g_Slo[(size_t)BATCH * DINP];
__device__ __nv_bfloat16 g_W0h[(size_t)DINP * HID];
__device__ __nv_bfloat16 g_W0l[(size_t)DINP * HID];
__device__ __nv_bfloat16 g_W1h[(size_t)HID * HID];
__device__ __nv_bfloat16 g_W1l[(size_t)HID * HID];
__device__ __nv_bfloat16 g_W2h[(size_t)HID * NACTP];
__device__ __nv_bfloat16 g_W2l[(size_t)HID * NACTP];
__device__ __nv_bfloat16 g_H0h[(size_t)BATCH * HID];
__device__ __nv_bfloat16 g_H0l[(size_t)BATCH * HID];
__device__ __nv_bfloat16 g_H1h[(size_t)BATCH * HID];
__device__ __nv_bfloat16 g_H1l[(size_t)BATCH * HID];
__device__ float g_logits[(size_t)BATCH * NACT];

// ---------------------------------------------------------------------------
// Split/pad: fp32 [R,C] -> bf16 hi/lo [Rpad, Cpad], zero outside [R,C].
// ---------------------------------------------------------------------------
__global__ void split_pad_kernel(const float* __restrict__ src,
                                 __nv_bfloat16* __restrict__ hi,
                                 __nv_bfloat16* __restrict__ lo,
                                 int R, int C, int Rpad, int Cpad)
{
    size_t total = (size_t)Rpad * Cpad;
    for (size_t idx = (size_t)blockIdx.x * blockDim.x + threadIdx.x;
         idx < total; idx += (size_t)gridDim.x * blockDim.x) {
        int r = (int)(idx / Cpad);
        int c = (int)(idx % Cpad);
        float v = 0.0f;
        if (r < R && c < C) v = src[(size_t)r * C + c];
        __nv_bfloat16 h = __float2bfloat16(v);
        __nv_bfloat16 l = __float2bfloat16(v - __bfloat162float(h));
        hi[idx] = h;
        lo[idx] = l;
    }
}

// ---------------------------------------------------------------------------
// PTX helpers
// ---------------------------------------------------------------------------
__device__ __forceinline__ void ldsm_x4(uint32_t& r0, uint32_t& r1,
                                        uint32_t& r2, uint32_t& r3,
                                        const void* p)
{
    uint32_t a = (uint32_t)__cvta_generic_to_shared(p);
    asm volatile("ldmatrix.sync.aligned.m8n8.x4.shared.b16 {%0,%1,%2,%3}, [%4];"
                 : "=r"(r0), "=r"(r1), "=r"(r2), "=r"(r3) : "r"(a));
}

__device__ __forceinline__ void ldsm_x4_trans(uint32_t& r0, uint32_t& r1,
                                              uint32_t& r2, uint32_t& r3,
                                              const void* p)
{
    uint32_t a = (uint32_t)__cvta_generic_to_shared(p);
    asm volatile("ldmatrix.sync.aligned.m8n8.x4.trans.shared.b16 {%0,%1,%2,%3}, [%4];"
                 : "=r"(r0), "=r"(r1), "=r"(r2), "=r"(r3) : "r"(a));
}

__device__ __forceinline__ void mma16816(float* d, const uint32_t* a, const uint32_t* b)
{
    asm volatile(
        "mma.sync.aligned.m16n8k16.row.col.f32.bf16.bf16.f32 "
        "{%0,%1,%2,%3}, {%4,%5,%6,%7}, {%8,%9}, {%0,%1,%2,%3};"
        : "+f"(d[0]), "+f"(d[1]), "+f"(d[2]), "+f"(d[3])
        : "r"(a[0]), "r"(a[1]), "r"(a[2]), "r"(a[3]),
          "r"(b[0]), "r"(b[1]));
}

__device__ __forceinline__ void cp16(uint32_t dst, const void* src)
{
    asm volatile("cp.async.cg.shared.global [%0], [%1], 16;"
                 :: "r"(dst), "l"(src));
}
__device__ __forceinline__ void cp_commit() {
    asm volatile("cp.async.commit_group;" ::: "memory");
}
__device__ __forceinline__ void cp_wait1() {
    asm volatile("cp.async.wait_group 1;" ::: "memory");
}

// ---------------------------------------------------------------------------
// bf16-split tensor-core GEMM, 2-stage cp.async double buffer.
//   C = act( (Ahi+Alo) @ (Bhi+Blo) + bias ),  lo*lo product dropped.
// 128x128 CTA tile, BK=32, 256 threads = 8 warps (2x4), warp tile 64x32.
// K pre-padded to mult of 32; scratch tensors fully zero-padded -> no guards.
// ---------------------------------------------------------------------------
#define GBM 128
#define GBN 128
#define GBK 32
#define APAD 40    // A smem row stride (halves)
#define BPAD 136   // B smem row stride (halves)
#define A_HALVES (GBM * APAD)                       // 5120 per tensor
#define B_HALVES (GBK * BPAD)                       // 4352 per tensor
#define STAGE_HALVES (2 * A_HALVES + 2 * B_HALVES)  // 18944 halves = 37888 B
#define GEMM_SMEM_BYTES (2 * STAGE_HALVES * 2)      // 75776 B

template <int OUT>
__global__ void __launch_bounds__(256)
gemm_bf16_split(const __nv_bfloat16* __restrict__ Ahi,
                const __nv_bfloat16* __restrict__ Alo, int lda,
                const __nv_bfloat16* __restrict__ Bhi,
                const __nv_bfloat16* __restrict__ Blo, int ldb,
                const float* __restrict__ bias,
                __nv_bfloat16* __restrict__ Chi,
                __nv_bfloat16* __restrict__ Clo,
                float* __restrict__ Cf, int ldc, int Nvalid,
                int kIters)
{
    extern __shared__ __nv_bfloat16 sm[];

    const int tid  = threadIdx.x;
    const int lane = tid & 31;
    const int wid  = tid >> 5;
    const int warpRow = (wid & 1) * 64;
    const int warpCol = (wid >> 1) * 32;
    const int bm = blockIdx.y * GBM;
    const int bn = blockIdx.x * GBN;

    const uint32_t sbase = (uint32_t)__cvta_generic_to_shared(sm);

    // Per-thread cp.async indices: 2 A-vectors + 2 B-vectors per tensor.
    const int i0 = tid, i1 = 256 + tid;
    const int aR0 = i0 >> 2, aK0 = (i0 & 3) << 3;    // A: 4 vecs/row
    const int aR1 = i1 >> 2, aK1 = (i1 & 3) << 3;
    const int bR0 = i0 >> 4, bN0 = (i0 & 15) << 3;   // B: 16 vecs/row
    const int bR1 = i1 >> 4, bN1 = (i1 & 15) << 3;

    float acc[4][4][4];
#pragma unroll
    for (int i = 0; i < 4; i++)
#pragma unroll
        for (int j = 0; j < 4; j++)
#pragma unroll
            for (int f = 0; f < 4; f++) acc[i][j][f] = 0.0f;

    // ldmatrix lane addressing
    const int lm  = lane >> 3;
    const int lr  = lane & 7;
    const int aRowOff = (lm & 1) * 8 + lr;
    const int aColOff = (lm >> 1) * 8;
    const int bRowOff = (lm & 1) * 8 + lr;
    const int bColOff = (lm >> 1) * 8;

    auto load_stage = [&](int kt, int s) {
        const int k0 = kt * GBK;
        const uint32_t sb  = sbase + (uint32_t)(s * STAGE_HALVES) * 2u;
        const uint32_t oAh = sb;
        const uint32_t oAl = sb + A_HALVES * 2u;
        const uint32_t oBh = sb + 2u * A_HALVES * 2u;
        const uint32_t oBl = oBh + B_HALVES * 2u;
        cp16(oAh + (uint32_t)(aR0 * APAD + aK0) * 2u, Ahi + (size_t)(bm + aR0) * lda + k0 + aK0);
        cp16(oAh + (uint32_t)(aR1 * APAD + aK1) * 2u, Ahi + (size_t)(bm + aR1) * lda + k0 + aK1);
        cp16(oAl + (uint32_t)(aR0 * APAD + aK0) * 2u, Alo + (size_t)(bm + aR0) * lda + k0 + aK0);
        cp16(oAl + (uint32_t)(aR1 * APAD + aK1) * 2u, Alo + (size_t)(bm + aR1) * lda + k0 + aK1);
        cp16(oBh + (uint32_t)(bR0 * BPAD + bN0) * 2u, Bhi + (size_t)(k0 + bR0) * ldb + bn + bN0);
        cp16(oBh + (uint32_t)(bR1 * BPAD + bN1) * 2u, Bhi + (size_t)(k0 + bR1) * ldb + bn + bN1);
        cp16(oBl + (uint32_t)(bR0 * BPAD + bN0) * 2u, Blo + (size_t)(k0 + bR0) * ldb + bn + bN0);
        cp16(oBl + (uint32_t)(bR1 * BPAD + bN1) * 2u, Blo + (size_t)(k0 + bR1) * ldb + bn + bN1);
    };

    // Prologue: stage 0 in flight.
    load_stage(0, 0);
    cp_commit();

    for (int kt = 0; kt < kIters; kt++) {
        // Issue next chunk's loads (stage was freed by trailing barrier of kt-1)
        if (kt + 1 < kIters) load_stage(kt + 1, (kt + 1) & 1);
        cp_commit();                 // one group per iteration (possibly empty)
        cp_wait1();                  // chunk kt's group complete
        __syncthreads();

        const int s = kt & 1;
        __nv_bfloat16* sAh = sm + s * STAGE_HALVES;
        __nv_bfloat16* sAl = sAh + A_HALVES;
        __nv_bfloat16* sBh = sAl + A_HALVES;
        __nv_bfloat16* sBl = sBh + B_HALVES;

#pragma unroll
        for (int ks = 0; ks < GBK; ks += 16) {
            uint32_t ahi[4][4], alo[4][4], bhi[4][2], blo[4][2];
#pragma unroll
            for (int mi = 0; mi < 4; mi++) {
                int row = warpRow + mi * 16 + aRowOff;
                int col = ks + aColOff;
                ldsm_x4(ahi[mi][0], ahi[mi][1], ahi[mi][2], ahi[mi][3], sAh + row * APAD + col);
                ldsm_x4(alo[mi][0], alo[mi][1], alo[mi][2], alo[mi][3], sAl + row * APAD + col);
            }
#pragma unroll
            for (int ni = 0; ni < 2; ni++) {
                int krow = ks + bRowOff;
                int col  = warpCol + ni * 16 + bColOff;
                uint32_t r0, r1, r2, r3;
                ldsm_x4_trans(r0, r1, r2, r3, sBh + krow * BPAD + col);
                bhi[ni * 2 + 0][0] = r0; bhi[ni * 2 + 0][1] = r1;
                bhi[ni * 2 + 1][0] = r2; bhi[ni * 2 + 1][1] = r3;
                ldsm_x4_trans(r0, r1, r2, r3, sBl + krow * BPAD + col);
                blo[ni * 2 + 0][0] = r0; blo[ni * 2 + 0][1] = r1;
                blo[ni * 2 + 1][0] = r2; blo[ni * 2 + 1][1] = r3;
            }
#pragma unroll
            for (int mi = 0; mi < 4; mi++)
#pragma unroll
                for (int nj = 0; nj < 4; nj++) {
                    mma16816(acc[mi][nj], ahi[mi], bhi[nj]);
                    mma16816(acc[mi][nj], ahi[mi], blo[nj]);
                    mma16816(acc[mi][nj], alo[mi], bhi[nj]);
                }
        }
        __syncthreads();             // stage readable done -> next load may overwrite
    }

    // Epilogue
    const int gid = lane >> 2;
    const int tg  = lane & 3;
#pragma unroll
    for (int mi = 0; mi < 4; mi++) {
#pragma unroll
        for (int nj = 0; nj < 4; nj++) {
            int col = bn + warpCol + nj * 8 + tg * 2;
            float bv0 = 0.0f, bv1 = 0.0f;
            if (OUT == 0 || col + 1 < Nvalid) {
                bv0 = bias[col];
                bv1 = bias[col + 1];
            }
#pragma unroll
            for (int half = 0; half < 2; half++) {
                int row = bm + warpRow + mi * 16 + gid + half * 8;
                float v0 = acc[mi][nj][half * 2 + 0] + bv0;
                float v1 = acc[mi][nj][half * 2 + 1] + bv1;
                if (OUT == 0) {
                    v0 = fmaxf(v0, 0.0f);
                    v1 = fmaxf(v1, 0.0f);
                    __nv_bfloat16 h0 = __float2bfloat16(v0);
                    __nv_bfloat16 h1 = __float2bfloat16(v1);
                    __nv_bfloat162 hp; hp.x = h0; hp.y = h1;
                    __nv_bfloat162 lp;
                    lp.x = __float2bfloat16(v0 - __bfloat162float(h0));
                    lp.y = __float2bfloat16(v1 - __bfloat162float(h1));
                    *(__nv_bfloat162*)&Chi[(size_t)row * ldc + col] = hp;
                    *(__nv_bfloat162*)&Clo[(size_t)row * ldc + col] = lp;
                } else {
                    if (col + 1 < Nvalid) {
                        float2 v; v.x = v0; v.y = v1;
                        *(float2*)&Cf[(size_t)row * ldc + col] = v;
                    }
                }
            }
        }
    }
}

// ---------------------------------------------------------------------------
// Sampler: incremental log-softmax-without-replacement
// ---------------------------------------------------------------------------
__global__ void __launch_bounds__(64)
sampler_kernel(const float* __restrict__ logits,
               const int* __restrict__ idxR, const int* __restrict__ lenR,
               const int* __restrict__ idxS, const int* __restrict__ lenS,
               float* __restrict__ out)
{
    const int b = blockIdx.x;
    const int w = threadIdx.x >> 5;
    const int lane = threadIdx.x & 31;

    const float* lrow = logits + (size_t)b * NACT + w * NHEAD;
    const int* sidx = (w == 0 ? idxR : idxS) + (size_t)b * KSEQ;
    const int slen = (w == 0 ? lenR : lenS)[b];

    float m = -INFINITY;
    for (int i = lane; i < NHEAD; i += 32) m = fmaxf(m, lrow[i]);
#pragma unroll
    for (int off = 16; off > 0; off >>= 1)
        m = fmaxf(m, __shfl_xor_sync(0xFFFFFFFFu, m, off));

    float S1 = 0.0f, S2 = 0.0f;
    for (int i = lane; i < NHEAD; i += 32) {
        float l = lrow[i] - m;
        float e = expf(l);
        S1 += e;
        S2 += l * e;
    }
#pragma unroll
    for (int off = 16; off > 0; off >>= 1) {
        S1 += __shfl_xor_sync(0xFFFFFFFFu, S1, off);
        S2 += __shfl_xor_sync(0xFFFFFFFFu, S2, off);
    }

    __shared__ float sh[4];
    if (lane == 0) {
        float logp = 0.0f, ent = 0.0f;
        for (int t = 0; t < slen; t++) {
            float lS1 = logf(S1);
            ent += lS1 - S2 / S1;
            int id = sidx[t];
            if (id >= 0) {
                float l = lrow[id] - m;
                logp += l - lS1;
                float e = expf(l);
                S1 -= e;
                S2 -= l * e;
            }
        }
        sh[w * 2 + 0] = logp;
        sh[w * 2 + 1] = ent;
    }
    __syncthreads();
    if (threadIdx.x == 0) {
        out[b]         = sh[0] + sh[2];
        out[BATCH + b] = sh[1] + sh[3];
    }
}

// ---------------------------------------------------------------------------
// Launch
// ---------------------------------------------------------------------------
extern "C" void kernel_launch(void* const* d_in, const int* in_sizes, int n_in,
                              void* d_out, int out_size)
{
    const float* state = (const float*)d_in[0];
    const float* W0    = (const float*)d_in[1];
    const float* b0    = (const float*)d_in[2];
    const float* W1    = (const float*)d_in[3];
    const float* b1    = (const float*)d_in[4];
    const float* W2    = (const float*)d_in[5];
    const float* b2    = (const float*)d_in[6];
    const int* seq_idx_R = (const int*)d_in[7];
    const int* seq_len_R = (const int*)d_in[8];
    const int* seq_idx_S = (const int*)d_in[9];
    const int* seq_len_S = (const int*)d_in[10];
    float* out = (float*)d_out;

    __nv_bfloat16 *Shi, *Slo, *W0h, *W0l, *W1h, *W1l, *W2h, *W2l;
    __nv_bfloat16 *H0h, *H0l, *H1h, *H1l;
    float* lg;
    cudaGetSymbolAddress((void**)&Shi, g_Shi);
    cudaGetSymbolAddress((void**)&Slo, g_Slo);
    cudaGetSymbolAddress((void**)&W0h, g_W0h);
    cudaGetSymbolAddress((void**)&W0l, g_W0l);
    cudaGetSymbolAddress((void**)&W1h, g_W1h);
    cudaGetSymbolAddress((void**)&W1l, g_W1l);
    cudaGetSymbolAddress((void**)&W2h, g_W2h);
    cudaGetSymbolAddress((void**)&W2l, g_W2l);
    cudaGetSymbolAddress((void**)&H0h, g_H0h);
    cudaGetSymbolAddress((void**)&H0l, g_H0l);
    cudaGetSymbolAddress((void**)&H1h, g_H1h);
    cudaGetSymbolAddress((void**)&H1l, g_H1l);
    cudaGetSymbolAddress((void**)&lg, g_logits);

    cudaFuncSetAttribute(gemm_bf16_split<0>, cudaFuncAttributeMaxDynamicSharedMemorySize, GEMM_SMEM_BYTES);
    cudaFuncSetAttribute(gemm_bf16_split<1>, cudaFuncAttributeMaxDynamicSharedMemorySize, GEMM_SMEM_BYTES);

    // Split + pad inputs/weights to bf16 hi/lo
    split_pad_kernel<<<2048, 256>>>(state, Shi, Slo, BATCH, DIN, BATCH, DINP);
    split_pad_kernel<<<1024, 256>>>(W0, W0h, W0l, DIN, HID, DINP, HID);
    split_pad_kernel<<<1024, 256>>>(W1, W1h, W1l, HID, HID, HID, HID);
    split_pad_kernel<<<1024, 256>>>(W2, W2h, W2l, HID, NACT, HID, NACTP);

    dim3 blk(256);
    dim3 g1(HID / GBN, BATCH / GBM);     // (8, 64)
    dim3 g3(NACTP / GBN, BATCH / GBM);   // (9, 64)

    gemm_bf16_split<0><<<g1, blk, GEMM_SMEM_BYTES>>>(Shi, Slo, DINP, W0h, W0l, HID, b0,
                                                     H0h, H0l, nullptr, HID, HID, DINP / GBK);
    gemm_bf16_split<0><<<g1, blk, GEMM_SMEM_BYTES>>>(H0h, H0l, HID, W1h, W1l, HID, b1,
                                                     H1h, H1l, nullptr, HID, HID, HID / GBK);
    gemm_bf16_split<1><<<g3, blk, GEMM_SMEM_BYTES>>>(H1h, H1l, HID, W2h, W2l, NACTP, b2,
                                                     nullptr, nullptr, lg, NACT, NACT, HID / GBK);

    sampler_kernel<<<BATCH, 64>>>(lg, seq_idx_R, seq_len_R,
                                  seq_idx_S, seq_len_S, out);
}

// round 7
// speedup vs baseline: 1.6047x; 1.6047x over previous
#include <cuda_runtime.h>
#include <cuda_bf16.h>
#include <math.h>
#include <stdint.h>

// Problem constants
#define BATCH 8192
#define DIN   1025
#define HID   1024
#define NACT  1026
#define NHEAD 513
#define KSEQ  32

// Padded dims (K padded to mult of 64 for BK=64 chunks)
#define DINP  1088
#define NACTP 1152

// ---------------------------------------------------------------------------
// Scratch (allocation-free: __device__ globals)
// ---------------------------------------------------------------------------
__device__ __nv_bfloat16 g_Shi[(size_t)BATCH * DINP];
__device__ __nv_bfloat16 g_Slo[(size_t)BATCH * DINP];
__device__ __nv_bfloat16 g_W0h[(size_t)DINP * HID];
__device__ __nv_bfloat16 g_W0l[(size_t)DINP * HID];
__device__ __nv_bfloat16 g_W1h[(size_t)HID * HID];
__device__ __nv_bfloat16 g_W1l[(size_t)HID * HID];
__device__ __nv_bfloat16 g_W2h[(size_t)HID * NACTP];
__device__ __nv_bfloat16 g_W2l[(size_t)HID * NACTP];
__device__ __nv_bfloat16 g_H0h[(size_t)BATCH * HID];
__device__ __nv_bfloat16 g_H0l[(size_t)BATCH * HID];
__device__ __nv_bfloat16 g_H1h[(size_t)BATCH * HID];
__device__ __nv_bfloat16 g_H1l[(size_t)BATCH * HID];
__device__ float g_logits[(size_t)BATCH * NACT];

// ---------------------------------------------------------------------------
// Split/pad: fp32 [R,C] -> bf16 hi/lo [Rpad, Cpad], zero outside [R,C].
// ---------------------------------------------------------------------------
__global__ void split_pad_kernel(const float* __restrict__ src,
                                 __nv_bfloat16* __restrict__ hi,
                                 __nv_bfloat16* __restrict__ lo,
                                 int R, int C, int Rpad, int Cpad)
{
    size_t total = (size_t)Rpad * Cpad;
    for (size_t idx = (size_t)blockIdx.x * blockDim.x + threadIdx.x;
         idx < total; idx += (size_t)gridDim.x * blockDim.x) {
        int r = (int)(idx / Cpad);
        int c = (int)(idx % Cpad);
        float v = 0.0f;
        if (r < R && c < C) v = src[(size_t)r * C + c];
        __nv_bfloat16 h = __float2bfloat16(v);
        __nv_bfloat16 l = __float2bfloat16(v - __bfloat162float(h));
        hi[idx] = h;
        lo[idx] = l;
    }
}

// ---------------------------------------------------------------------------
// PTX helpers
// ---------------------------------------------------------------------------
__device__ __forceinline__ void ldsm_x4(uint32_t& r0, uint32_t& r1,
                                        uint32_t& r2, uint32_t& r3,
                                        const void* p)
{
    uint32_t a = (uint32_t)__cvta_generic_to_shared(p);
    asm volatile("ldmatrix.sync.aligned.m8n8.x4.shared.b16 {%0,%1,%2,%3}, [%4];"
                 : "=r"(r0), "=r"(r1), "=r"(r2), "=r"(r3) : "r"(a));
}

__device__ __forceinline__ void ldsm_x4_trans(uint32_t& r0, uint32_t& r1,
                                              uint32_t& r2, uint32_t& r3,
                                              const void* p)
{
    uint32_t a = (uint32_t)__cvta_generic_to_shared(p);
    asm volatile("ldmatrix.sync.aligned.m8n8.x4.trans.shared.b16 {%0,%1,%2,%3}, [%4];"
                 : "=r"(r0), "=r"(r1), "=r"(r2), "=r"(r3) : "r"(a));
}

__device__ __forceinline__ void mma16816(float* d, const uint32_t* a, const uint32_t* b)
{
    asm volatile(
        "mma.sync.aligned.m16n8k16.row.col.f32.bf16.bf16.f32 "
        "{%0,%1,%2,%3}, {%4,%5,%6,%7}, {%8,%9}, {%0,%1,%2,%3};"
        : "+f"(d[0]), "+f"(d[1]), "+f"(d[2]), "+f"(d[3])
        : "r"(a[0]), "r"(a[1]), "r"(a[2]), "r"(a[3]),
          "r"(b[0]), "r"(b[1]));
}

// ---------------------------------------------------------------------------
// bf16-split tensor-core GEMM (single buffer, plain LDG/STS, 2 barriers per
// K-chunk; relies on 2 CTAs/SM for load/compute overlap).
//   C = act( (Ahi+Alo) @ (Bhi+Blo) + bias ),  lo*lo product dropped.
// 128x128 CTA tile, BK=64, 256 threads = 8 warps (2x4), warp tile 64x32.
// K pre-padded to mult of 64; scratch tensors fully zero-padded -> no guards.
// ---------------------------------------------------------------------------
#define GBM 128
#define GBN 128
#define GBK 64
#define APAD 72    // A smem row stride (halves): 144B rows, conflict-free ldsm
#define BPAD 136   // B smem row stride (halves): 272B rows, conflict-free ldsm
#define A_HALVES (GBM * APAD)                 // 9216 per tensor
#define B_HALVES (GBK * BPAD)                 // 8704 per tensor
#define GEMM_SMEM_BYTES ((2 * A_HALVES + 2 * B_HALVES) * 2)  // 71680 B

template <int OUT>
__global__ void __launch_bounds__(256, 2)
gemm_bf16_split(const __nv_bfloat16* __restrict__ Ahi,
                const __nv_bfloat16* __restrict__ Alo, int lda,
                const __nv_bfloat16* __restrict__ Bhi,
                const __nv_bfloat16* __restrict__ Blo, int ldb,
                const float* __restrict__ bias,
                __nv_bfloat16* __restrict__ Chi,
                __nv_bfloat16* __restrict__ Clo,
                float* __restrict__ Cf, int ldc, int Nvalid,
                int kIters)
{
    extern __shared__ __nv_bfloat16 sm[];
    __nv_bfloat16* sAh = sm;
    __nv_bfloat16* sAl = sAh + A_HALVES;
    __nv_bfloat16* sBh = sAl + A_HALVES;
    __nv_bfloat16* sBl = sBh + B_HALVES;

    const int tid  = threadIdx.x;
    const int lane = tid & 31;
    const int wid  = tid >> 5;
    const int warpRow = (wid & 1) * 64;
    const int warpCol = (wid >> 1) * 32;
    const int bm = blockIdx.y * GBM;
    const int bn = blockIdx.x * GBN;

    float acc[4][4][4];
#pragma unroll
    for (int i = 0; i < 4; i++)
#pragma unroll
        for (int j = 0; j < 4; j++)
#pragma unroll
            for (int f = 0; f < 4; f++) acc[i][j][f] = 0.0f;

    // ldmatrix lane addressing
    const int lm  = lane >> 3;
    const int lr  = lane & 7;
    const int aRowOff = (lm & 1) * 8 + lr;
    const int aColOff = (lm >> 1) * 8;
    const int bRowOff = (lm & 1) * 8 + lr;
    const int bColOff = (lm >> 1) * 8;

    for (int kt = 0; kt < kIters; kt++) {
        const int k0 = kt * GBK;

        // Load A: 128 rows x 64 halves = 1024 uint4 per tensor; 4/thread.
        // B: 64 rows x 128 halves = 1024 uint4 per tensor; 4/thread.
#pragma unroll
        for (int v = 0; v < 4; v++) {
            int idx = v * 256 + tid;
            int ar = idx >> 3, ak = (idx & 7) << 3;
            int br = idx >> 4, bn8 = (idx & 15) << 3;
            const size_t ga = (size_t)(bm + ar) * lda + k0 + ak;
            const size_t gb = (size_t)(k0 + br) * ldb + bn + bn8;
            *(uint4*)(sAh + ar * APAD + ak) = *(const uint4*)(Ahi + ga);
            *(uint4*)(sAl + ar * APAD + ak) = *(const uint4*)(Alo + ga);
            *(uint4*)(sBh + br * BPAD + bn8) = *(const uint4*)(Bhi + gb);
            *(uint4*)(sBl + br * BPAD + bn8) = *(const uint4*)(Blo + gb);
        }
        __syncthreads();

#pragma unroll
        for (int ks = 0; ks < GBK; ks += 16) {
            // B fragments for this ks (held across the mi loop)
            uint32_t bhi[4][2], blo[4][2];
#pragma unroll
            for (int ni = 0; ni < 2; ni++) {
                const __nv_bfloat16* pb = sBh + (ks + bRowOff) * BPAD
                                        + warpCol + ni * 16 + bColOff;
                uint32_t r0, r1, r2, r3;
                ldsm_x4_trans(r0, r1, r2, r3, pb);
                bhi[ni * 2 + 0][0] = r0; bhi[ni * 2 + 0][1] = r1;
                bhi[ni * 2 + 1][0] = r2; bhi[ni * 2 + 1][1] = r3;
                // sBl lives exactly B_HALVES elements after sBh
                ldsm_x4_trans(r0, r1, r2, r3, pb + B_HALVES);
                blo[ni * 2 + 0][0] = r0; blo[ni * 2 + 0][1] = r1;
                blo[ni * 2 + 1][0] = r2; blo[ni * 2 + 1][1] = r3;
            }
            // A fragments per mi (small live set -> fits 128 regs at occ 2)
#pragma unroll
            for (int mi = 0; mi < 4; mi++) {
                const int row = warpRow + mi * 16 + aRowOff;
                uint32_t ahi[4], alo[4];
                ldsm_x4(ahi[0], ahi[1], ahi[2], ahi[3],
                        sAh + row * APAD + ks + aColOff);
                ldsm_x4(alo[0], alo[1], alo[2], alo[3],
                        sAl + row * APAD + ks + aColOff);
#pragma unroll
                for (int nj = 0; nj < 4; nj++) {
                    mma16816(acc[mi][nj], ahi, bhi[nj]);
                    mma16816(acc[mi][nj], ahi, blo[nj]);
                    mma16816(acc[mi][nj], alo, bhi[nj]);
                }
            }
        }
        __syncthreads();
    }

    // Epilogue: c-frag layout -> bias + act -> coalesced stores
    const int gid = lane >> 2;
    const int tg  = lane & 3;
#pragma unroll
    for (int mi = 0; mi < 4; mi++) {
#pragma unroll
        for (int nj = 0; nj < 4; nj++) {
            int col = bn + warpCol + nj * 8 + tg * 2;
            float bv0 = 0.0f, bv1 = 0.0f;
            if (OUT == 0 || col + 1 < Nvalid) {
                bv0 = bias[col];
                bv1 = bias[col + 1];
            }
#pragma unroll
            for (int half = 0; half < 2; half++) {
                int row = bm + warpRow + mi * 16 + gid + half * 8;
                float v0 = acc[mi][nj][half * 2 + 0] + bv0;
                float v1 = acc[mi][nj][half * 2 + 1] + bv1;
                if (OUT == 0) {
                    v0 = fmaxf(v0, 0.0f);
                    v1 = fmaxf(v1, 0.0f);
                    __nv_bfloat16 h0 = __float2bfloat16(v0);
                    __nv_bfloat16 h1 = __float2bfloat16(v1);
                    __nv_bfloat162 hp; hp.x = h0; hp.y = h1;
                    __nv_bfloat162 lp;
                    lp.x = __float2bfloat16(v0 - __bfloat162float(h0));
                    lp.y = __float2bfloat16(v1 - __bfloat162float(h1));
                    *(__nv_bfloat162*)&Chi[(size_t)row * ldc + col] = hp;
                    *(__nv_bfloat162*)&Clo[(size_t)row * ldc + col] = lp;
                } else {
                    if (col + 1 < Nvalid) {
                        float2 v; v.x = v0; v.y = v1;
                        *(float2*)&Cf[(size_t)row * ldc + col] = v;
                    }
                }
            }
        }
    }
}

// ---------------------------------------------------------------------------
// Sampler: incremental log-softmax-without-replacement
// ---------------------------------------------------------------------------
__global__ void __launch_bounds__(64)
sampler_kernel(const float* __restrict__ logits,
               const int* __restrict__ idxR, const int* __restrict__ lenR,
               const int* __restrict__ idxS, const int* __restrict__ lenS,
               float* __restrict__ out)
{
    const int b = blockIdx.x;
    const int w = threadIdx.x >> 5;
    const int lane = threadIdx.x & 31;

    const float* lrow = logits + (size_t)b * NACT + w * NHEAD;
    const int* sidx = (w == 0 ? idxR : idxS) + (size_t)b * KSEQ;
    const int slen = (w == 0 ? lenR : lenS)[b];

    float m = -INFINITY;
    for (int i = lane; i < NHEAD; i += 32) m = fmaxf(m, lrow[i]);
#pragma unroll
    for (int off = 16; off > 0; off >>= 1)
        m = fmaxf(m, __shfl_xor_sync(0xFFFFFFFFu, m, off));

    float S1 = 0.0f, S2 = 0.0f;
    for (int i = lane; i < NHEAD; i += 32) {
        float l = lrow[i] - m;
        float e = expf(l);
        S1 += e;
        S2 += l * e;
    }
#pragma unroll
    for (int off = 16; off > 0; off >>= 1) {
        S1 += __shfl_xor_sync(0xFFFFFFFFu, S1, off);
        S2 += __shfl_xor_sync(0xFFFFFFFFu, S2, off);
    }

    __shared__ float sh[4];
    if (lane == 0) {
        float logp = 0.0f, ent = 0.0f;
        for (int t = 0; t < slen; t++) {
            float lS1 = logf(S1);
            ent += lS1 - S2 / S1;
            int id = sidx[t];
            if (id >= 0) {
                float l = lrow[id] - m;
                logp += l - lS1;
                float e = expf(l);
                S1 -= e;
                S2 -= l * e;
            }
        }
        sh[w * 2 + 0] = logp;
        sh[w * 2 + 1] = ent;
    }
    __syncthreads();
    if (threadIdx.x == 0) {
        out[b]         = sh[0] + sh[2];
        out[BATCH + b] = sh[1] + sh[3];
    }
}

// ---------------------------------------------------------------------------
// Launch
// ---------------------------------------------------------------------------
extern "C" void kernel_launch(void* const* d_in, const int* in_sizes, int n_in,
                              void* d_out, int out_size)
{
    const float* state = (const float*)d_in[0];
    const float* W0    = (const float*)d_in[1];
    const float* b0    = (const float*)d_in[2];
    const float* W1    = (const float*)d_in[3];
    const float* b1    = (const float*)d_in[4];
    const float* W2    = (const float*)d_in[5];
    const float* b2    = (const float*)d_in[6];
    const int* seq_idx_R = (const int*)d_in[7];
    const int* seq_len_R = (const int*)d_in[8];
    const int* seq_idx_S = (const int*)d_in[9];
    const int* seq_len_S = (const int*)d_in[10];
    float* out = (float*)d_out;

    __nv_bfloat16 *Shi, *Slo, *W0h, *W0l, *W1h, *W1l, *W2h, *W2l;
    __nv_bfloat16 *H0h, *H0l, *H1h, *H1l;
    float* lg;
    cudaGetSymbolAddress((void**)&Shi, g_Shi);
    cudaGetSymbolAddress((void**)&Slo, g_Slo);
    cudaGetSymbolAddress((void**)&W0h, g_W0h);
    cudaGetSymbolAddress((void**)&W0l, g_W0l);
    cudaGetSymbolAddress((void**)&W1h, g_W1h);
    cudaGetSymbolAddress((void**)&W1l, g_W1l);
    cudaGetSymbolAddress((void**)&W2h, g_W2h);
    cudaGetSymbolAddress((void**)&W2l, g_W2l);
    cudaGetSymbolAddress((void**)&H0h, g_H0h);
    cudaGetSymbolAddress((void**)&H0l, g_H0l);
    cudaGetSymbolAddress((void**)&H1h, g_H1h);
    cudaGetSymbolAddress((void**)&H1l, g_H1l);
    cudaGetSymbolAddress((void**)&lg, g_logits);

    cudaFuncSetAttribute(gemm_bf16_split<0>, cudaFuncAttributeMaxDynamicSharedMemorySize, GEMM_SMEM_BYTES);
    cudaFuncSetAttribute(gemm_bf16_split<1>, cudaFuncAttributeMaxDynamicSharedMemorySize, GEMM_SMEM_BYTES);

    // Split + pad inputs/weights to bf16 hi/lo
    split_pad_kernel<<<2048, 256>>>(state, Shi, Slo, BATCH, DIN, BATCH, DINP);
    split_pad_kernel<<<1024, 256>>>(W0, W0h, W0l, DIN, HID, DINP, HID);
    split_pad_kernel<<<1024, 256>>>(W1, W1h, W1l, HID, HID, HID, HID);
    split_pad_kernel<<<1024, 256>>>(W2, W2h, W2l, HID, NACT, HID, NACTP);

    dim3 blk(256);
    dim3 g1(HID / GBN, BATCH / GBM);     // (8, 64)
    dim3 g3(NACTP / GBN, BATCH / GBM);   // (9, 64)

    gemm_bf16_split<0><<<g1, blk, GEMM_SMEM_BYTES>>>(Shi, Slo, DINP, W0h, W0l, HID, b0,
                                                     H0h, H0l, nullptr, HID, HID, DINP / GBK);
    gemm_bf16_split<0><<<g1, blk, GEMM_SMEM_BYTES>>>(H0h, H0l, HID, W1h, W1l, HID, b1,
                                                     H1h, H1l, nullptr, HID, HID, HID / GBK);
    gemm_bf16_split<1><<<g3, blk, GEMM_SMEM_BYTES>>>(H1h, H1l, HID, W2h, W2l, NACTP, b2,
                                                     nullptr, nullptr, lg, NACT, NACT, HID / GBK);

    sampler_kernel<<<BATCH, 64>>>(lg, seq_idx_R, seq_len_R,
                                  seq_idx_S, seq_len_S, out);
}